// round 1
// baseline (speedup 1.0000x reference)
#include <cuda_runtime.h>
#include <cstdint>

// Problem dims (fixed by reference)
#define BB 256
#define TT 1024
#define DD 64
#define HH 128

typedef unsigned long long ull;

static constexpr size_t BT  = (size_t)BB * TT;        // 262144
static constexpr size_t BTH = (size_t)BB * TT * HH;   // 33554432

// Scratch for precomputed input projections (no cudaMalloc allowed)
__device__ float g_gK[BTH];   // gate_x_K
__device__ float g_z [BTH];   // tanh(gate_x_z)

__device__ __forceinline__ void fma2(ull& acc, ull a, ull b) {
    asm("fma.rn.f32x2 %0, %1, %2, %0;" : "+l"(acc) : "l"(a), "l"(b));
}
__device__ __forceinline__ float2 unpk(ull v) {
    float2 f;
    asm("mov.b64 {%0, %1}, %2;" : "=f"(f.x), "=f"(f.y) : "l"(v));
    return f;
}
// Overflow-safe fast tanh: tanh(x) = sign(x) * (1-e)/(1+e), e = exp(-2|x|) in (0,1]
__device__ __forceinline__ float fast_tanh(float x) {
    float a = fabsf(x);
    float e = __expf(-2.0f * a);
    float t = (1.0f - e) / (1.0f + e);
    return copysignf(t, x);
}
__device__ __forceinline__ float fast_sigmoid(float x) {
    return 1.0f / (1.0f + __expf(-x));  // x<<0: exp->inf -> 0; x>>0: -> 1
}

// ---------------------------------------------------------------------------
// Kernel 1: input projections. Each CTA: 64 rows of x; thread i = h-index i.
// Thread keeps W_xK[i][:] and W_xz[i][:] in registers (f32x2 packed).
// ---------------------------------------------------------------------------
__global__ void __launch_bounds__(128)
proj_kernel(const float* __restrict__ x,
            const float* __restrict__ WxK, const float* __restrict__ bxK,
            const float* __restrict__ Wxz, const float* __restrict__ bxz)
{
    constexpr int ROWS = 64;
    __shared__ __align__(16) float xs[ROWS * DD];   // 16 KB

    const int i = threadIdx.x;                       // h index 0..127
    const size_t row0 = (size_t)blockIdx.x * ROWS;

    // Cooperative load of the x tile (64 rows x 64 floats = 1024 float4)
    const float4* xg  = (const float4*)(x + row0 * DD);
    float4*       xs4 = (float4*)xs;
#pragma unroll
    for (int k = 0; k < 8; k++) xs4[i + 128 * k] = xg[i + 128 * k];

    // W rows into registers, f32x2 packed: wK[m] = (W[i][2m], W[i][2m+1])
    ull wK[32], wz[32];
    {
        const ull* wKr = (const ull*)(WxK + i * DD);
        const ull* wzr = (const ull*)(Wxz + i * DD);
#pragma unroll
        for (int m = 0; m < 32; m++) { wK[m] = wKr[m]; wz[m] = wzr[m]; }
    }
    const float bK = bxK[i];
    const float bz = bxz[i];
    __syncthreads();

    const ull* xs8 = (const ull*)xs;
    for (int r = 0; r < ROWS; r++) {
        ull aK = 0ull, az = 0ull;   // (0.f, 0.f)
        const ull* xr = xs8 + r * 32;
#pragma unroll
        for (int m = 0; m < 32; m++) {
            ull xv = xr[m];          // broadcast LDS
            fma2(aK, wK[m], xv);
            fma2(az, wz[m], xv);
        }
        float2 k2 = unpk(aK), z2 = unpk(az);
        float gK = k2.x + k2.y + bK;
        float gz = z2.x + z2.y + bz;
        size_t n = (row0 + r) * HH + i;
        g_gK[n] = gK;
        g_z[n]  = fast_tanh(gz);
    }
}

// ---------------------------------------------------------------------------
// Kernel 2: sequential scan. One CTA per batch, thread i = h-index i.
// W_hK row i lives in 128 registers (f32x2). h state double-buffered in smem.
// 2-step-ahead register prefetch of (gK, z) from global scratch.
// ---------------------------------------------------------------------------
__global__ void __launch_bounds__(128, 2)
scan_kernel(const float* __restrict__ WhK, const float* __restrict__ bhK,
            float* __restrict__ out, int dup)
{
    __shared__ __align__(16) float hbuf[2][HH];

    const int i = threadIdx.x;
    const int b = blockIdx.x;

    // W_hK row i into registers: w[m] = (W[i][2m], W[i][2m+1])
    ull w[64];
    {
        const ull* wr = (const ull*)(WhK + i * HH);
#pragma unroll
        for (int m = 0; m < 64; m++) w[m] = wr[m];
    }
    const float bh = bhK[i];

    hbuf[0][i] = 0.0f;
    float h_i = 0.0f;

    const float* gKp = g_gK + (size_t)b * TT * HH + i;
    const float* zp  = g_z  + (size_t)b * TT * HH + i;
    float* op  = out + (size_t)b * TT * HH + i;
    float* op2 = op + BTH;

    // software pipeline depth 2
    float gA = gKp[0],  zA = zp[0];
    float gB = gKp[HH], zB = zp[HH];

    __syncthreads();

    int cur = 0;
    for (int t = 0; t < TT; t++) {
        const float g = gA, z = zA;
        gA = gB; zA = zB;
        if (t + 2 < TT) {
            gB = gKp[(size_t)(t + 2) * HH];
            zB = zp [(size_t)(t + 2) * HH];
        }

        // matvec: gate_h = sum_j h[j] * W[i][j]
        const ulonglong2* h16 = (const ulonglong2*)hbuf[cur];
        ull a0 = 0ull, a1 = 0ull;
#pragma unroll
        for (int k = 0; k < 32; k++) {
            ulonglong2 hv = h16[k];  // broadcast LDS.128: h[4k..4k+3]
            fma2(a0, w[2 * k],     hv.x);
            fma2(a1, w[2 * k + 1], hv.y);
        }
        float2 p0 = unpk(a0), p1 = unpk(a1);
        float ghK = p0.x + p0.y + p1.x + p1.y + bh;

        float kg  = fast_sigmoid(g + ghK);
        float pre = h_i + kg * (z - h_i);
        h_i = fast_tanh(pre);

        op[(size_t)t * HH] = h_i;
        if (dup) op2[(size_t)t * HH] = h_i;

        cur ^= 1;
        hbuf[cur][i] = h_i;
        __syncthreads();
    }
}

// ---------------------------------------------------------------------------
extern "C" void kernel_launch(void* const* d_in, const int* in_sizes, int n_in,
                              void* d_out, int out_size)
{
    const float* x   = (const float*)d_in[0];
    const float* WxK = (const float*)d_in[1];
    const float* bxK = (const float*)d_in[2];
    const float* Wxz = (const float*)d_in[3];
    const float* bxz = (const float*)d_in[4];
    const float* WhK = (const float*)d_in[5];
    const float* bhK = (const float*)d_in[6];
    float* out = (float*)d_out;

    proj_kernel<<<(int)(BT / 64), 128>>>(x, WxK, bxK, Wxz, bxz);

    const int dup = ((size_t)out_size >= 2 * BTH) ? 1 : 0;
    scan_kernel<<<BB, 128>>>(WhK, bhK, out, dup);
}